// round 12
// baseline (speedup 1.0000x reference)
#include <cuda_runtime.h>
#include <cuda_fp16.h>
#include <math.h>

// PixelCNN fused forward — R12: BOTH convs on tensor cores, TH=8, swizzled
// operand layouts (XOR 16B-chunk swizzle proven in R11), smem overlay.
//   conv1: X2[m][16] = [xhi(7-wide kx window,0-pad)|xlo], ky taps = row
//          shifts of 66. B1m=[Wh;Wh] -> xhi*Wh+xlo*Wh in one MMA; B1l=[Wl;0].
//   conv2: Ahi/Alo[m][16ic], taps = shifts {0,1,2,66,67}; 3-term hi/lo.
// 3 CTAs/SM, dynamic smem 73472B (sx overlaid with B2).

#define IMG_H 64
#define IMG_W 64
#define NCH   16
#define TH    8
#define XRR   12            // x halo rows r0-4 .. r0+7
#define XC    72            // cols -4..67
#define X2R   816           // 12*66=792 used, reads to 805, pad 816
#define AROWS 596

// dynamic smem offsets (bytes)
#define U_OFF   0                    // union: sx (3456) / B2h+B2l (5120)
#define X2_OFF  5120                 // 816*32 = 26112
#define AHI_OFF (X2_OFF + 26112)     // 31232
#define ALO_OFF (AHI_OFF + 19072)    // 50304
#define B1M_OFF (ALO_OFF + 19072)    // 69376
#define B1L_OFF (B1M_OFF + 2048)     // 71424
#define SMEM_TOTAL (B1L_OFF + 2048)  // 73472

struct PackedW {
    float w1t[24][16];    // [tap][oc]
    float w2[16][5][16];  // [ic][tap][oc]
    float b1[16];
    float b2[16];
    float w3[16];
    float b3;
    float pad[3];
};

__device__   PackedW g_w;
__constant__ PackedW c_w;

__device__ __forceinline__ unsigned smem_u32(const void* p) {
    unsigned a;
    asm("{ .reg .u64 t; cvta.to.shared.u64 t, %1; cvt.u32.u64 %0, t; }"
        : "=r"(a) : "l"(p));
    return a;
}
__device__ __forceinline__ void ldsm_x4(unsigned addr, unsigned& r0, unsigned& r1,
                                        unsigned& r2, unsigned& r3) {
    asm volatile("ldmatrix.sync.aligned.m8n8.x4.shared.b16 {%0,%1,%2,%3}, [%4];"
                 : "=r"(r0), "=r"(r1), "=r"(r2), "=r"(r3) : "r"(addr));
}
__device__ __forceinline__ void ldsm_x4t(unsigned addr, unsigned& r0, unsigned& r1,
                                         unsigned& r2, unsigned& r3) {
    asm volatile("ldmatrix.sync.aligned.m8n8.x4.trans.shared.b16 {%0,%1,%2,%3}, [%4];"
                 : "=r"(r0), "=r"(r1), "=r"(r2), "=r"(r3) : "r"(addr));
}
__device__ __forceinline__ void mma16816(float& d0, float& d1, float& d2, float& d3,
                                         unsigned a0, unsigned a1, unsigned a2, unsigned a3,
                                         unsigned b0, unsigned b1) {
    asm volatile(
        "mma.sync.aligned.m16n8k16.row.col.f32.f16.f16.f32 "
        "{%0,%1,%2,%3}, {%4,%5,%6,%7}, {%8,%9}, {%0,%1,%2,%3};"
        : "+f"(d0), "+f"(d1), "+f"(d2), "+f"(d3)
        : "r"(a0), "r"(a1), "r"(a2), "r"(a3), "r"(b0), "r"(b1));
}

// ---- prep: pack masked weights into g_w ----
__global__ void pixelcnn_prep(const float* __restrict__ w1, const float* __restrict__ b1,
                              const float* __restrict__ w2, const float* __restrict__ b2,
                              const float* __restrict__ w3, const float* __restrict__ b3)
{
    float* dst = reinterpret_cast<float*>(&g_w);
    const int tid = threadIdx.x;

    for (int idx = tid; idx < 24 * NCH; idx += 256) {
        int t = idx / NCH, oc = idx % NCH;
        int ky, kx;
        if (t < 21) { ky = t / 7; kx = t % 7; }
        else        { ky = 3;     kx = t - 21; }
        dst[idx] = w1[oc * 49 + ky * 7 + kx];
    }
    for (int idx = tid; idx < NCH * 5 * NCH; idx += 256) {
        int ic  = idx / (5 * NCH);
        int rem = idx % (5 * NCH);
        int t   = rem / NCH;
        int oc  = rem % NCH;
        int ky, kx;
        if (t < 3) { ky = 0; kx = t; }
        else       { ky = 1; kx = t - 3; }
        dst[384 + idx] = w2[((oc * NCH + ic) * 3 + ky) * 3 + kx];
    }
    if (tid < NCH) {
        dst[1664 + tid] = b1[tid];
        dst[1680 + tid] = b2[tid];
        dst[1696 + tid] = w3[tid];
    }
    if (tid == 0) dst[1712] = b3[0];
}

__global__ __launch_bounds__(256, 3)
void pixelcnn_fused(const float* __restrict__ x, float* __restrict__ out)
{
    extern __shared__ __align__(16) char smem_buf[];
    float*  sx  = reinterpret_cast<float*>(smem_buf + U_OFF);     // [12][72]
    __half* B2h = reinterpret_cast<__half*>(smem_buf + U_OFF);    // [5][16][16] (after sx dead)
    __half* B2l = reinterpret_cast<__half*>(smem_buf + U_OFF + 2560);
    __half* X2  = reinterpret_cast<__half*>(smem_buf + X2_OFF);   // [816][16] swizzled
    __half* Ahi = reinterpret_cast<__half*>(smem_buf + AHI_OFF);  // [596][16] swizzled
    __half* Alo = reinterpret_cast<__half*>(smem_buf + ALO_OFF);  // [596][16] swizzled
    __half* B1m = reinterpret_cast<__half*>(smem_buf + B1M_OFF);  // [4][16][16]
    __half* B1l = reinterpret_cast<__half*>(smem_buf + B1L_OFF);  // [4][16][16]

    const int tid  = threadIdx.x;
    const int lane = tid & 31;
    const int wid  = tid >> 5;
    const int img  = blockIdx.y;
    const int r0   = blockIdx.x * TH;
    const float* __restrict__ xim = x + img * (IMG_H * IMG_W);
    const float* cwf = reinterpret_cast<const float*>(&c_w);

    // lane-role constants
    const unsigned arow  = lane & 15;
    const unsigned akoff = (lane >> 4) * 16;
    const unsigned brow  = lane & 15;
    const unsigned bnoff = (lane >> 4) * 16;
    const int cb = (lane & 3) * 2;
    const int g  = lane >> 2;

    // ---- phase 1: x halo + B1 mats + zero pads ----
    for (int idx = tid; idx < XRR * XC; idx += 256) {
        int i = idx / XC, j = idx % XC;
        int gr = r0 - 4 + i;
        int gc = j - 4;
        float v = 0.0f;
        if (gr >= 0 && gr < IMG_H && gc >= 0 && gc < IMG_W)
            v = xim[gr * IMG_W + gc];
        sx[idx] = v;
    }
    for (int idx = tid; idx < 4 * 16 * 16; idx += 256) {
        int ky = idx >> 8;
        int kr = (idx >> 4) & 15;
        int oc = idx & 15;
        int kx = kr & 7;
        float wv = 0.0f;
        if (kx < 7) {
            if (ky < 3)      wv = cwf[(ky * 7 + kx) * 16 + oc];
            else if (kx < 3) wv = cwf[(21 + kx) * 16 + oc];
        }
        __half hi = __float2half_rn(wv);
        __half lo = __float2half_rn(wv - __half2float(hi));
        B1m[idx] = hi;
        B1l[idx] = (kr < 8) ? lo : __half(0.0f);
    }
    // zero X2 pad rows 792..815
    for (int idx = tid; idx < 24 * 8; idx += 256)
        reinterpret_cast<unsigned*>(X2)[792 * 8 + idx] = 0u;
    // zero A rows 594,595
    if (tid < 16) {
        int rr = 594 + (tid >> 3);
        int cc = (tid & 7) * 2;
        *reinterpret_cast<unsigned*>(&Ahi[rr * 16 + cc]) = 0u;
        *reinterpret_cast<unsigned*>(&Alo[rr * 16 + cc]) = 0u;
    }
    __syncthreads();

    // ---- phase 2: build X2[m][16] = [xhi(8)|xlo(8)] with chunk swizzle ----
    for (int m = tid; m < 792; m += 256) {
        const int xr = m / 66;
        const int hc = m - xr * 66;
        unsigned hiw[4], low[4];
        #pragma unroll
        for (int q = 0; q < 4; q++) {
            float v0 = sx[xr * 72 + hc + q * 2];
            float v1 = (q * 2 + 1 < 7) ? sx[xr * 72 + hc + q * 2 + 1] : 0.0f;
            float2 vm = make_float2(v0, v1);
            __half2 hh = __float22half2_rn(vm);
            float2 back = __half22float2(hh);
            __half2 hl = __float22half2_rn(make_float2(vm.x - back.x, vm.y - back.y));
            hiw[q] = *reinterpret_cast<unsigned*>(&hh);
            low[q] = *reinterpret_cast<unsigned*>(&hl);
        }
        const int s0 = (m >> 2) & 1;
        uint4* row = reinterpret_cast<uint4*>(X2 + m * 16);
        row[s0]     = make_uint4(hiw[0], hiw[1], hiw[2], hiw[3]);  // logical chunk 0 (hi)
        row[1 - s0] = make_uint4(low[0], low[1], low[2], low[3]);  // logical chunk 1 (lo)
    }
    __syncthreads();

    // ---- phase 3a: build B2 mats (over dead sx region) ----
    for (int idx = tid; idx < 16 * 5 * 16; idx += 256) {
        int ic  = idx / 80;
        int rem = idx % 80;
        int t   = rem / 16;
        int oc  = rem % 16;
        float v = cwf[384 + ic * 80 + t * 16 + oc];
        __half hi = __float2half_rn(v);
        __half lo = __float2half_rn(v - __half2float(hi));
        B2h[(t * 16 + ic) * 16 + oc] = hi;
        B2l[(t * 16 + ic) * 16 + oc] = lo;
    }

    // ---- phase 3b: conv1 via MMA -> Ahi/Alo ----
    {
        const unsigned x2_b  = smem_u32(X2);
        const unsigned b1m_b = smem_u32(B1m);
        const unsigned b1l_b = smem_u32(B1l);

        unsigned bm[4][4], blw[4][4];
        #pragma unroll
        for (int ky = 0; ky < 4; ky++) {
            const unsigned bbyte = (unsigned)ky * 512 + brow * 32 + bnoff;
            ldsm_x4t(b1m_b + bbyte, bm[ky][0], bm[ky][1], bm[ky][2], bm[ky][3]);
            ldsm_x4t(b1l_b + bbyte, blw[ky][0], blw[ky][1], blw[ky][2], blw[ky][3]);
        }
        float b1c[4];
        #pragma unroll
        for (int j = 0; j < 2; j++) {
            b1c[j]     = cwf[1664 + cb + j];
            b1c[2 + j] = cwf[1664 + cb + 8 + j];
        }

        for (int tile = wid; tile < 38; tile += 8) {
            const int m0 = tile * 16;
            float d0[4] = {0.f, 0.f, 0.f, 0.f};
            float d1[4] = {0.f, 0.f, 0.f, 0.f};

            #pragma unroll
            for (int ky = 0; ky < 4; ky++) {
                const unsigned row   = (unsigned)(m0 + ky * 66) + arow;
                const unsigned rbyte = row * 32 + (akoff ^ ((row & 4u) << 2));
                unsigned a0, a1, a2, a3;
                ldsm_x4(x2_b + rbyte, a0, a1, a2, a3);

                mma16816(d0[0], d0[1], d0[2], d0[3], a0, a1, a2, a3, bm[ky][0], bm[ky][1]);
                mma16816(d1[0], d1[1], d1[2], d1[3], a0, a1, a2, a3, bm[ky][2], bm[ky][3]);
                mma16816(d0[0], d0[1], d0[2], d0[3], a0, a1, a2, a3, blw[ky][0], blw[ky][1]);
                mma16816(d1[0], d1[1], d1[2], d1[3], a0, a1, a2, a3, blw[ky][2], blw[ky][3]);
            }

            // epilogue: +b1, relu, mask, hi/lo split -> swizzled Ahi/Alo
            #pragma unroll
            for (int s = 0; s < 2; s++) {
                const int m = m0 + g + s * 8;
                if (m >= 594) continue;
                const int hr = m / 66;
                const int hc = m - hr * 66;
                const bool ok = (hc >= 1) && (hc < 65) && (r0 - 1 + hr >= 0);
                float v0 = (s == 0 ? d0[0] : d0[2]) + b1c[0];
                float v1 = (s == 0 ? d0[1] : d0[3]) + b1c[1];
                float v2 = (s == 0 ? d1[0] : d1[2]) + b1c[2];
                float v3 = (s == 0 ? d1[1] : d1[3]) + b1c[3];
                v0 = ok ? fmaxf(v0, 0.f) : 0.f;
                v1 = ok ? fmaxf(v1, 0.f) : 0.f;
                v2 = ok ? fmaxf(v2, 0.f) : 0.f;
                v3 = ok ? fmaxf(v3, 0.f) : 0.f;

                float2 pA = make_float2(v0, v1), pB = make_float2(v2, v3);
                __half2 hA = __float22half2_rn(pA);
                __half2 hB = __float22half2_rn(pB);
                float2 bA = __half22float2(hA), bB = __half22float2(hB);
                __half2 lA = __float22half2_rn(make_float2(pA.x - bA.x, pA.y - bA.y));
                __half2 lB = __float22half2_rn(make_float2(pB.x - bB.x, pB.y - bB.y));

                const int s0 = (m >> 2) & 1;
                // logical col cb -> chunk0, cb+8 -> chunk1; physical chunk = logical^s0
                *reinterpret_cast<unsigned*>(&Ahi[m * 16 + s0 * 8 + cb])       = *reinterpret_cast<unsigned*>(&hA);
                *reinterpret_cast<unsigned*>(&Ahi[m * 16 + (1 - s0) * 8 + cb]) = *reinterpret_cast<unsigned*>(&hB);
                *reinterpret_cast<unsigned*>(&Alo[m * 16 + s0 * 8 + cb])       = *reinterpret_cast<unsigned*>(&lA);
                *reinterpret_cast<unsigned*>(&Alo[m * 16 + (1 - s0) * 8 + cb]) = *reinterpret_cast<unsigned*>(&lB);
            }
        }
    }
    __syncthreads();

    // ---- phase 4: conv2 via MMA + conv3 + sigmoid ----
    {
        const unsigned ahi_b = smem_u32(Ahi);
        const unsigned alo_b = smem_u32(Alo);
        const unsigned b2h_b = smem_u32(B2h);
        const unsigned b2l_b = smem_u32(B2l);

        unsigned bh[5][4], bl[5][4];
        #pragma unroll
        for (int t = 0; t < 5; t++) {
            const unsigned bbyte = (unsigned)t * 512 + brow * 32 + bnoff;
            ldsm_x4t(b2h_b + bbyte, bh[t][0], bh[t][1], bh[t][2], bh[t][3]);
            ldsm_x4t(b2l_b + bbyte, bl[t][0], bl[t][1], bl[t][2], bl[t][3]);
        }

        float b2c[4], w3c[4];
        #pragma unroll
        for (int j = 0; j < 2; j++) {
            b2c[j]     = cwf[1680 + cb + j];
            b2c[2 + j] = cwf[1680 + cb + 8 + j];
            w3c[j]     = cwf[1696 + cb + j];
            w3c[2 + j] = cwf[1696 + cb + 8 + j];
        }
        const float b3v = cwf[1712];
        const int shifts[5] = {0, 1, 2, 66, 67};

        for (int tile = wid; tile < 33; tile += 8) {
            const int m0 = tile * 16;
            float d0[4] = {0.f, 0.f, 0.f, 0.f};
            float d1[4] = {0.f, 0.f, 0.f, 0.f};

            #pragma unroll
            for (int t = 0; t < 5; t++) {
                const unsigned row   = (unsigned)(m0 + shifts[t]) + arow;
                const unsigned rbyte = row * 32 + (akoff ^ ((row & 4u) << 2));
                unsigned ah0, ah1, ah2, ah3, al0, al1, al2, al3;
                ldsm_x4(ahi_b + rbyte, ah0, ah1, ah2, ah3);
                ldsm_x4(alo_b + rbyte, al0, al1, al2, al3);

                mma16816(d0[0], d0[1], d0[2], d0[3], ah0, ah1, ah2, ah3, bh[t][0], bh[t][1]);
                mma16816(d1[0], d1[1], d1[2], d1[3], ah0, ah1, ah2, ah3, bh[t][2], bh[t][3]);
                mma16816(d0[0], d0[1], d0[2], d0[3], ah0, ah1, ah2, ah3, bl[t][0], bl[t][1]);
                mma16816(d1[0], d1[1], d1[2], d1[3], ah0, ah1, ah2, ah3, bl[t][2], bl[t][3]);
                mma16816(d0[0], d0[1], d0[2], d0[3], al0, al1, al2, al3, bh[t][0], bh[t][1]);
                mma16816(d1[0], d1[1], d1[2], d1[3], al0, al1, al2, al3, bh[t][2], bh[t][3]);
            }

            float zA = 0.f, zB = 0.f;
            #pragma unroll
            for (int j = 0; j < 2; j++) {
                zA += fmaxf(d0[j]     + b2c[j],     0.0f) * w3c[j];
                zA += fmaxf(d1[j]     + b2c[2 + j], 0.0f) * w3c[2 + j];
                zB += fmaxf(d0[2 + j] + b2c[j],     0.0f) * w3c[j];
                zB += fmaxf(d1[2 + j] + b2c[2 + j], 0.0f) * w3c[2 + j];
            }
            zA += __shfl_xor_sync(0xffffffffu, zA, 1);
            zA += __shfl_xor_sync(0xffffffffu, zA, 2);
            zB += __shfl_xor_sync(0xffffffffu, zB, 1);
            zB += __shfl_xor_sync(0xffffffffu, zB, 2);

            if ((lane & 3) == 0) {
                #pragma unroll
                for (int s = 0; s < 2; s++) {
                    const int m = m0 + g + s * 8;
                    const float z = (s == 0 ? zA : zB) + b3v;
                    const int r = m / 66;
                    const int c = m - r * 66;
                    if (c < 64 && r < 8) {
                        float y = 1.0f / (1.0f + __expf(-z));
                        out[img * (IMG_H * IMG_W) + (r0 + r) * IMG_W + c] = y;
                    }
                }
            }
        }
    }
}

extern "C" void kernel_launch(void* const* d_in, const int* in_sizes, int n_in,
                              void* d_out, int out_size) {
    const float* x  = (const float*)d_in[0];
    const float* w1 = (const float*)d_in[1];
    const float* b1 = (const float*)d_in[2];
    const float* w2 = (const float*)d_in[3];
    const float* b2 = (const float*)d_in[4];
    const float* w3 = (const float*)d_in[5];
    const float* b3 = (const float*)d_in[6];
    float* out = (float*)d_out;

    cudaFuncSetAttribute(pixelcnn_fused,
                         cudaFuncAttributeMaxDynamicSharedMemorySize, SMEM_TOTAL);
    cudaFuncSetAttribute(pixelcnn_fused,
                         cudaFuncAttributePreferredSharedMemoryCarveout, 100);

    pixelcnn_prep<<<1, 256>>>(w1, b1, w2, b2, w3, b3);

    void* g_addr = nullptr;
    cudaGetSymbolAddress(&g_addr, g_w);
    cudaMemcpyToSymbolAsync(c_w, g_addr, sizeof(PackedW), 0,
                            cudaMemcpyDeviceToDevice, 0);

    dim3 grid(IMG_H / TH, 1024);  // (8, 1024)
    pixelcnn_fused<<<grid, 256, SMEM_TOTAL>>>(x, out);
}

// round 13
// speedup vs baseline: 1.0651x; 1.0651x over previous
#include <cuda_runtime.h>
#include <cuda_fp16.h>
#include <math.h>

// PixelCNN fused forward — R13: both convs on tensor cores, TH=8, swizzled
// layouts, smem 54.4KB -> 4 CTAs/SM.
//   conv1: X2[m][16]=[xhi|xlo]; B1m=[Wh;Wh], B1l=[Wl;0]  (full precision)
//   conv2: A[m][16] = fp16(relu(h1)); 2-term B split (Ah*Bh + Ah*Bl);
//          dropped Al*Bh term (~5e-4 rel on h2, ~1e-4 on output; thr 1e-3)
// ky taps = row shifts of 66; conv2 taps = shifts {0,1,2,66,67}.

#define IMG_H 64
#define IMG_W 64
#define NCH   16
#define TH    8
#define XRR   12            // x halo rows r0-4 .. r0+7
#define XC    72

// dynamic smem offsets (bytes)
#define U_OFF   0                    // union: sx (3456) / B2h+B2l (5120)
#define X2_OFF  5120                 // 816*32 = 26112
#define AHI_OFF (X2_OFF + 26112)     // 31232 ; 596*32 = 19072
#define B1M_OFF (AHI_OFF + 19072)    // 50304
#define B1L_OFF (B1M_OFF + 2048)     // 52352
#define SMEM_TOTAL (B1L_OFF + 2048)  // 54400

struct PackedW {
    float w1t[24][16];    // [tap][oc]
    float w2[16][5][16];  // [ic][tap][oc]
    float b1[16];
    float b2[16];
    float w3[16];
    float b3;
    float pad[3];
};

__device__   PackedW g_w;
__constant__ PackedW c_w;

__device__ __forceinline__ unsigned smem_u32(const void* p) {
    unsigned a;
    asm("{ .reg .u64 t; cvta.to.shared.u64 t, %1; cvt.u32.u64 %0, t; }"
        : "=r"(a) : "l"(p));
    return a;
}
__device__ __forceinline__ void ldsm_x4(unsigned addr, unsigned& r0, unsigned& r1,
                                        unsigned& r2, unsigned& r3) {
    asm volatile("ldmatrix.sync.aligned.m8n8.x4.shared.b16 {%0,%1,%2,%3}, [%4];"
                 : "=r"(r0), "=r"(r1), "=r"(r2), "=r"(r3) : "r"(addr));
}
__device__ __forceinline__ void ldsm_x4t(unsigned addr, unsigned& r0, unsigned& r1,
                                         unsigned& r2, unsigned& r3) {
    asm volatile("ldmatrix.sync.aligned.m8n8.x4.trans.shared.b16 {%0,%1,%2,%3}, [%4];"
                 : "=r"(r0), "=r"(r1), "=r"(r2), "=r"(r3) : "r"(addr));
}
__device__ __forceinline__ void mma16816(float& d0, float& d1, float& d2, float& d3,
                                         unsigned a0, unsigned a1, unsigned a2, unsigned a3,
                                         unsigned b0, unsigned b1) {
    asm volatile(
        "mma.sync.aligned.m16n8k16.row.col.f32.f16.f16.f32 "
        "{%0,%1,%2,%3}, {%4,%5,%6,%7}, {%8,%9}, {%0,%1,%2,%3};"
        : "+f"(d0), "+f"(d1), "+f"(d2), "+f"(d3)
        : "r"(a0), "r"(a1), "r"(a2), "r"(a3), "r"(b0), "r"(b1));
}

// ---- prep: pack masked weights into g_w ----
__global__ void pixelcnn_prep(const float* __restrict__ w1, const float* __restrict__ b1,
                              const float* __restrict__ w2, const float* __restrict__ b2,
                              const float* __restrict__ w3, const float* __restrict__ b3)
{
    float* dst = reinterpret_cast<float*>(&g_w);
    const int tid = threadIdx.x;

    for (int idx = tid; idx < 24 * NCH; idx += 256) {
        int t = idx / NCH, oc = idx % NCH;
        int ky, kx;
        if (t < 21) { ky = t / 7; kx = t % 7; }
        else        { ky = 3;     kx = t - 21; }
        dst[idx] = w1[oc * 49 + ky * 7 + kx];
    }
    for (int idx = tid; idx < NCH * 5 * NCH; idx += 256) {
        int ic  = idx / (5 * NCH);
        int rem = idx % (5 * NCH);
        int t   = rem / NCH;
        int oc  = rem % NCH;
        int ky, kx;
        if (t < 3) { ky = 0; kx = t; }
        else       { ky = 1; kx = t - 3; }
        dst[384 + idx] = w2[((oc * NCH + ic) * 3 + ky) * 3 + kx];
    }
    if (tid < NCH) {
        dst[1664 + tid] = b1[tid];
        dst[1680 + tid] = b2[tid];
        dst[1696 + tid] = w3[tid];
    }
    if (tid == 0) dst[1712] = b3[0];
}

__global__ __launch_bounds__(256, 4)
void pixelcnn_fused(const float* __restrict__ x, float* __restrict__ out)
{
    extern __shared__ __align__(16) char smem_buf[];
    float*  sx  = reinterpret_cast<float*>(smem_buf + U_OFF);     // [12][72]
    __half* B2h = reinterpret_cast<__half*>(smem_buf + U_OFF);    // [5][16][16] (after sx dead)
    __half* B2l = reinterpret_cast<__half*>(smem_buf + U_OFF + 2560);
    __half* X2  = reinterpret_cast<__half*>(smem_buf + X2_OFF);   // [816][16] swizzled
    __half* Ahi = reinterpret_cast<__half*>(smem_buf + AHI_OFF);  // [596][16] swizzled
    __half* B1m = reinterpret_cast<__half*>(smem_buf + B1M_OFF);  // [4][16][16]
    __half* B1l = reinterpret_cast<__half*>(smem_buf + B1L_OFF);  // [4][16][16]

    const int tid  = threadIdx.x;
    const int lane = tid & 31;
    const int wid  = tid >> 5;
    const int img  = blockIdx.y;
    const int r0   = blockIdx.x * TH;
    const float* __restrict__ xim = x + img * (IMG_H * IMG_W);
    const float* cwf = reinterpret_cast<const float*>(&c_w);

    const unsigned arow  = lane & 15;
    const unsigned akoff = (lane >> 4) * 16;
    const unsigned brow  = lane & 15;
    const unsigned bnoff = (lane >> 4) * 16;
    const int cb = (lane & 3) * 2;
    const int g  = lane >> 2;

    // ---- phase 1: x halo + B1 mats + zero pads ----
    for (int idx = tid; idx < XRR * XC; idx += 256) {
        int i = idx / XC, j = idx % XC;
        int gr = r0 - 4 + i;
        int gc = j - 4;
        float v = 0.0f;
        if (gr >= 0 && gr < IMG_H && gc >= 0 && gc < IMG_W)
            v = xim[gr * IMG_W + gc];
        sx[idx] = v;
    }
    for (int idx = tid; idx < 4 * 16 * 16; idx += 256) {
        int ky = idx >> 8;
        int kr = (idx >> 4) & 15;
        int oc = idx & 15;
        int kx = kr & 7;
        float wv = 0.0f;
        if (kx < 7) {
            if (ky < 3)      wv = cwf[(ky * 7 + kx) * 16 + oc];
            else if (kx < 3) wv = cwf[(21 + kx) * 16 + oc];
        }
        __half hi = __float2half_rn(wv);
        __half lo = __float2half_rn(wv - __half2float(hi));
        B1m[idx] = hi;
        B1l[idx] = (kr < 8) ? lo : __half(0.0f);
    }
    // zero X2 pad rows 792..815
    for (int idx = tid; idx < 24 * 8; idx += 256)
        reinterpret_cast<unsigned*>(X2)[792 * 8 + idx] = 0u;
    // zero A rows 594,595
    if (tid < 16) {
        int rr = 594 + (tid >> 3);
        int cc = (tid & 7) * 2;
        *reinterpret_cast<unsigned*>(&Ahi[rr * 16 + cc]) = 0u;
    }
    __syncthreads();

    // ---- phase 2: build X2[m][16] = [xhi(8)|xlo(8)] with chunk swizzle ----
    for (int m = tid; m < 792; m += 256) {
        const int xr = m / 66;
        const int hc = m - xr * 66;
        unsigned hiw[4], low[4];
        #pragma unroll
        for (int q = 0; q < 4; q++) {
            float v0 = sx[xr * 72 + hc + q * 2];
            float v1 = (q * 2 + 1 < 7) ? sx[xr * 72 + hc + q * 2 + 1] : 0.0f;
            float2 vm = make_float2(v0, v1);
            __half2 hh = __float22half2_rn(vm);
            float2 back = __half22float2(hh);
            __half2 hl = __float22half2_rn(make_float2(vm.x - back.x, vm.y - back.y));
            hiw[q] = *reinterpret_cast<unsigned*>(&hh);
            low[q] = *reinterpret_cast<unsigned*>(&hl);
        }
        const int s0 = (m >> 2) & 1;
        uint4* row = reinterpret_cast<uint4*>(X2 + m * 16);
        row[s0]     = make_uint4(hiw[0], hiw[1], hiw[2], hiw[3]);  // logical chunk 0 (hi)
        row[1 - s0] = make_uint4(low[0], low[1], low[2], low[3]);  // logical chunk 1 (lo)
    }
    __syncthreads();

    // ---- phase 3a: build B2 mats (over dead sx) ----
    for (int idx = tid; idx < 16 * 5 * 16; idx += 256) {
        int ic  = idx / 80;
        int rem = idx % 80;
        int t   = rem / 16;
        int oc  = rem % 16;
        float v = cwf[384 + ic * 80 + t * 16 + oc];
        __half hi = __float2half_rn(v);
        __half lo = __float2half_rn(v - __half2float(hi));
        B2h[(t * 16 + ic) * 16 + oc] = hi;
        B2l[(t * 16 + ic) * 16 + oc] = lo;
    }

    // ---- phase 3b: conv1 via MMA -> Ahi (fp16 only) ----
    {
        const unsigned x2_b  = smem_u32(X2);
        const unsigned b1m_b = smem_u32(B1m);
        const unsigned b1l_b = smem_u32(B1l);

        unsigned bm[4][4], blw[4][4];
        #pragma unroll
        for (int ky = 0; ky < 4; ky++) {
            const unsigned bbyte = (unsigned)ky * 512 + brow * 32 + bnoff;
            ldsm_x4t(b1m_b + bbyte, bm[ky][0], bm[ky][1], bm[ky][2], bm[ky][3]);
            ldsm_x4t(b1l_b + bbyte, blw[ky][0], blw[ky][1], blw[ky][2], blw[ky][3]);
        }
        float b1c[4];
        #pragma unroll
        for (int j = 0; j < 2; j++) {
            b1c[j]     = cwf[1664 + cb + j];
            b1c[2 + j] = cwf[1664 + cb + 8 + j];
        }

        for (int tile = wid; tile < 38; tile += 8) {
            const int m0 = tile * 16;
            float d0[4] = {0.f, 0.f, 0.f, 0.f};
            float d1[4] = {0.f, 0.f, 0.f, 0.f};

            #pragma unroll
            for (int ky = 0; ky < 4; ky++) {
                const unsigned row   = (unsigned)(m0 + ky * 66) + arow;
                const unsigned rbyte = row * 32 + (akoff ^ ((row & 4u) << 2));
                unsigned a0, a1, a2, a3;
                ldsm_x4(x2_b + rbyte, a0, a1, a2, a3);

                mma16816(d0[0], d0[1], d0[2], d0[3], a0, a1, a2, a3, bm[ky][0], bm[ky][1]);
                mma16816(d1[0], d1[1], d1[2], d1[3], a0, a1, a2, a3, bm[ky][2], bm[ky][3]);
                mma16816(d0[0], d0[1], d0[2], d0[3], a0, a1, a2, a3, blw[ky][0], blw[ky][1]);
                mma16816(d1[0], d1[1], d1[2], d1[3], a0, a1, a2, a3, blw[ky][2], blw[ky][3]);
            }

            // epilogue: +b1, relu, mask, fp16 -> swizzled Ahi
            #pragma unroll
            for (int s = 0; s < 2; s++) {
                const int m = m0 + g + s * 8;
                if (m >= 594) continue;
                const int hr = m / 66;
                const int hc = m - hr * 66;
                const bool ok = (hc >= 1) && (hc < 65) && (r0 - 1 + hr >= 0);
                float v0 = (s == 0 ? d0[0] : d0[2]) + b1c[0];
                float v1 = (s == 0 ? d0[1] : d0[3]) + b1c[1];
                float v2 = (s == 0 ? d1[0] : d1[2]) + b1c[2];
                float v3 = (s == 0 ? d1[1] : d1[3]) + b1c[3];
                v0 = ok ? fmaxf(v0, 0.f) : 0.f;
                v1 = ok ? fmaxf(v1, 0.f) : 0.f;
                v2 = ok ? fmaxf(v2, 0.f) : 0.f;
                v3 = ok ? fmaxf(v3, 0.f) : 0.f;

                __half2 hA = __float22half2_rn(make_float2(v0, v1));
                __half2 hB = __float22half2_rn(make_float2(v2, v3));

                const int s0 = (m >> 2) & 1;
                *reinterpret_cast<unsigned*>(&Ahi[m * 16 + s0 * 8 + cb])       = *reinterpret_cast<unsigned*>(&hA);
                *reinterpret_cast<unsigned*>(&Ahi[m * 16 + (1 - s0) * 8 + cb]) = *reinterpret_cast<unsigned*>(&hB);
            }
        }
    }
    __syncthreads();

    // ---- phase 4: conv2 via MMA (2-term) + conv3 + sigmoid ----
    {
        const unsigned ahi_b = smem_u32(Ahi);
        const unsigned b2h_b = smem_u32(B2h);
        const unsigned b2l_b = smem_u32(B2l);

        unsigned bh[5][4], bl[5][4];
        #pragma unroll
        for (int t = 0; t < 5; t++) {
            const unsigned bbyte = (unsigned)t * 512 + brow * 32 + bnoff;
            ldsm_x4t(b2h_b + bbyte, bh[t][0], bh[t][1], bh[t][2], bh[t][3]);
            ldsm_x4t(b2l_b + bbyte, bl[t][0], bl[t][1], bl[t][2], bl[t][3]);
        }

        float b2c[4], w3c[4];
        #pragma unroll
        for (int j = 0; j < 2; j++) {
            b2c[j]     = cwf[1680 + cb + j];
            b2c[2 + j] = cwf[1680 + cb + 8 + j];
            w3c[j]     = cwf[1696 + cb + j];
            w3c[2 + j] = cwf[1696 + cb + 8 + j];
        }
        const float b3v = cwf[1712];
        const int shifts[5] = {0, 1, 2, 66, 67};

        for (int tile = wid; tile < 33; tile += 8) {
            const int m0 = tile * 16;
            float d0[4] = {0.f, 0.f, 0.f, 0.f};
            float d1[4] = {0.f, 0.f, 0.f, 0.f};

            #pragma unroll
            for (int t = 0; t < 5; t++) {
                const unsigned row   = (unsigned)(m0 + shifts[t]) + arow;
                const unsigned rbyte = row * 32 + (akoff ^ ((row & 4u) << 2));
                unsigned ah0, ah1, ah2, ah3;
                ldsm_x4(ahi_b + rbyte, ah0, ah1, ah2, ah3);

                mma16816(d0[0], d0[1], d0[2], d0[3], ah0, ah1, ah2, ah3, bh[t][0], bh[t][1]);
                mma16816(d1[0], d1[1], d1[2], d1[3], ah0, ah1, ah2, ah3, bh[t][2], bh[t][3]);
                mma16816(d0[0], d0[1], d0[2], d0[3], ah0, ah1, ah2, ah3, bl[t][0], bl[t][1]);
                mma16816(d1[0], d1[1], d1[2], d1[3], ah0, ah1, ah2, ah3, bl[t][2], bl[t][3]);
            }

            float zA = 0.f, zB = 0.f;
            #pragma unroll
            for (int j = 0; j < 2; j++) {
                zA += fmaxf(d0[j]     + b2c[j],     0.0f) * w3c[j];
                zA += fmaxf(d1[j]     + b2c[2 + j], 0.0f) * w3c[2 + j];
                zB += fmaxf(d0[2 + j] + b2c[j],     0.0f) * w3c[j];
                zB += fmaxf(d1[2 + j] + b2c[2 + j], 0.0f) * w3c[2 + j];
            }
            zA += __shfl_xor_sync(0xffffffffu, zA, 1);
            zA += __shfl_xor_sync(0xffffffffu, zA, 2);
            zB += __shfl_xor_sync(0xffffffffu, zB, 1);
            zB += __shfl_xor_sync(0xffffffffu, zB, 2);

            if ((lane & 3) == 0) {
                #pragma unroll
                for (int s = 0; s < 2; s++) {
                    const int m = m0 + g + s * 8;
                    const float z = (s == 0 ? zA : zB) + b3v;
                    const int r = m / 66;
                    const int c = m - r * 66;
                    if (c < 64 && r < 8) {
                        float y = 1.0f / (1.0f + __expf(-z));
                        out[img * (IMG_H * IMG_W) + (r0 + r) * IMG_W + c] = y;
                    }
                }
            }
        }
    }
}

extern "C" void kernel_launch(void* const* d_in, const int* in_sizes, int n_in,
                              void* d_out, int out_size) {
    const float* x  = (const float*)d_in[0];
    const float* w1 = (const float*)d_in[1];
    const float* b1 = (const float*)d_in[2];
    const float* w2 = (const float*)d_in[3];
    const float* b2 = (const float*)d_in[4];
    const float* w3 = (const float*)d_in[5];
    const float* b3 = (const float*)d_in[6];
    float* out = (float*)d_out;

    cudaFuncSetAttribute(pixelcnn_fused,
                         cudaFuncAttributeMaxDynamicSharedMemorySize, SMEM_TOTAL);
    cudaFuncSetAttribute(pixelcnn_fused,
                         cudaFuncAttributePreferredSharedMemoryCarveout, 100);

    pixelcnn_prep<<<1, 256>>>(w1, b1, w2, b2, w3, b3);

    void* g_addr = nullptr;
    cudaGetSymbolAddress(&g_addr, g_w);
    cudaMemcpyToSymbolAsync(c_w, g_addr, sizeof(PackedW), 0,
                            cudaMemcpyDeviceToDevice, 0);

    dim3 grid(IMG_H / TH, 1024);  // (8, 1024)
    pixelcnn_fused<<<grid, 256, SMEM_TOTAL>>>(x, out);
}

// round 14
// speedup vs baseline: 1.2833x; 1.2048x over previous
#include <cuda_runtime.h>
#include <cuda_fp16.h>
#include <math.h>

// PixelCNN fused forward.
// R14 = R11 hybrid + validated 2-term conv2 (R13: rel_err 9.6e-6):
//   conv1 scalar FFMA2 on all 256 threads -> A = fp16(relu(h1)) only (no lo);
//   conv2 via mma.m16n8k16: A*Bh + A*Bl (weight split only), hoisted B frags;
//   XOR 16B-chunk swizzle on A (conflict-free ldsm).
// smem 28KB, 4 CTAs/SM.

#define IMG_H 64
#define IMG_W 64
#define NCH   16
#define TH    8
#define XR    (TH + 4)
#define XC    (IMG_W + 8)
#define AROWS 596          // 9*66 = 594 used + 2 pad

typedef unsigned long long u64;

struct PackedW {
    ulonglong2 w1t[24][4];    // [tap][ocgroup] fp32 pairs
    ulonglong2 w2[16][5][4];  // [ic][tap][ocgroup] fp32
    u64   b1[8];
    u64   b2[8];
    float w3[16];
    float b3;
    float pad[3];
};

__device__   PackedW g_w;
__constant__ PackedW c_w;

__device__ __forceinline__ u64 ffma2(u64 a, u64 b, u64 c) {
    u64 d;
    asm("fma.rn.f32x2 %0, %1, %2, %3;" : "=l"(d) : "l"(a), "l"(b), "l"(c));
    return d;
}
__device__ __forceinline__ u64 dup2(float x) {
    u64 d;
    asm("mov.b64 %0, {%1, %1};" : "=l"(d) : "f"(x));
    return d;
}
__device__ __forceinline__ float2 unpack2(u64 v) {
    float2 r;
    asm("mov.b64 {%0, %1}, %2;" : "=f"(r.x), "=f"(r.y) : "l"(v));
    return r;
}
__device__ __forceinline__ unsigned smem_u32(const void* p) {
    unsigned a;
    asm("{ .reg .u64 t; cvta.to.shared.u64 t, %1; cvt.u32.u64 %0, t; }"
        : "=r"(a) : "l"(p));
    return a;
}
__device__ __forceinline__ void ldsm_x4(unsigned addr, unsigned& r0, unsigned& r1,
                                        unsigned& r2, unsigned& r3) {
    asm volatile("ldmatrix.sync.aligned.m8n8.x4.shared.b16 {%0,%1,%2,%3}, [%4];"
                 : "=r"(r0), "=r"(r1), "=r"(r2), "=r"(r3) : "r"(addr));
}
__device__ __forceinline__ void ldsm_x4t(unsigned addr, unsigned& r0, unsigned& r1,
                                         unsigned& r2, unsigned& r3) {
    asm volatile("ldmatrix.sync.aligned.m8n8.x4.trans.shared.b16 {%0,%1,%2,%3}, [%4];"
                 : "=r"(r0), "=r"(r1), "=r"(r2), "=r"(r3) : "r"(addr));
}
__device__ __forceinline__ void mma16816(float& d0, float& d1, float& d2, float& d3,
                                         unsigned a0, unsigned a1, unsigned a2, unsigned a3,
                                         unsigned b0, unsigned b1) {
    asm volatile(
        "mma.sync.aligned.m16n8k16.row.col.f32.f16.f16.f32 "
        "{%0,%1,%2,%3}, {%4,%5,%6,%7}, {%8,%9}, {%0,%1,%2,%3};"
        : "+f"(d0), "+f"(d1), "+f"(d2), "+f"(d3)
        : "r"(a0), "r"(a1), "r"(a2), "r"(a3), "r"(b0), "r"(b1));
}

// ---- prep: pack masked weights into g_w (float view) ----
__global__ void pixelcnn_prep(const float* __restrict__ w1, const float* __restrict__ b1,
                              const float* __restrict__ w2, const float* __restrict__ b2,
                              const float* __restrict__ w3, const float* __restrict__ b3)
{
    float* dst = reinterpret_cast<float*>(&g_w);
    const int tid = threadIdx.x;

    for (int idx = tid; idx < 24 * NCH; idx += 256) {
        int t = idx / NCH, oc = idx % NCH;
        int ky, kx;
        if (t < 21) { ky = t / 7; kx = t % 7; }
        else        { ky = 3;     kx = t - 21; }
        dst[idx] = w1[oc * 49 + ky * 7 + kx];
    }
    for (int idx = tid; idx < NCH * 5 * NCH; idx += 256) {
        int ic  = idx / (5 * NCH);
        int rem = idx % (5 * NCH);
        int t   = rem / NCH;
        int oc  = rem % NCH;
        int ky, kx;
        if (t < 3) { ky = 0; kx = t; }
        else       { ky = 1; kx = t - 3; }
        dst[384 + idx] = w2[((oc * NCH + ic) * 3 + ky) * 3 + kx];
    }
    if (tid < NCH) {
        dst[1664 + tid] = b1[tid];
        dst[1680 + tid] = b2[tid];
        dst[1696 + tid] = w3[tid];
    }
    if (tid == 0) dst[1712] = b3[0];
}

__global__ __launch_bounds__(256, 4)
void pixelcnn_fused(const float* __restrict__ x, float* __restrict__ out)
{
    __shared__ __align__(16) float   sx[XR][XC];        // 3456 B
    __shared__ __align__(16) __half  A[AROWS][16];      // 19072 B (swizzled chunks)
    __shared__ __align__(16) __half  Bh[5][16][16];     // 2560 B
    __shared__ __align__(16) __half  Bl[5][16][16];     // 2560 B

    const int tid  = threadIdx.x;
    const int lane = tid & 31;
    const int wid  = tid >> 5;
    const int img  = blockIdx.y;
    const int r0   = blockIdx.x * TH;
    const float* __restrict__ xim = x + img * (IMG_H * IMG_W);
    const float* cwf = reinterpret_cast<const float*>(&c_w);

    // ---- load x halo tile (zero padded) ----
    for (int idx = tid; idx < XR * XC; idx += 256) {
        int i = idx / XC, j = idx % XC;
        int gr = r0 - 4 + i;
        int gc = j - 4;
        float v = 0.0f;
        if (gr >= 0 && gr < IMG_H && gc >= 0 && gc < IMG_W)
            v = xim[gr * IMG_W + gc];
        sx[i][j] = v;
    }

    // ---- build conv2 B matrices (hi/lo f16 weight split) ----
    for (int idx = tid; idx < 16 * 5 * 16; idx += 256) {
        int ic  = idx / 80;
        int rem = idx % 80;
        int t   = rem / 16;
        int oc  = rem % 16;
        float v = cwf[384 + ic * 80 + t * 16 + oc];
        __half hi = __float2half_rn(v);
        __half lo = __float2half_rn(v - __half2float(hi));
        Bh[t][ic][oc] = hi;
        Bl[t][ic][oc] = lo;
    }

    // ---- zero A pad rows (594, 595) ----
    if (tid < 16) {
        int rr = 594 + (tid >> 3);
        int cc = (tid & 7) * 2;
        *reinterpret_cast<unsigned*>(&A[rr][cc]) = 0u;
    }
    __syncthreads();

    // ---- conv1: all 256 threads, pixels strided by 256, all 16 oc ----
    for (int m = tid; m < 594; m += 256) {
        const int hr = m / 66;
        const int hc = m - hr * 66;
        const int grow = r0 - 1 + hr;
        const bool ok = (grow >= 0) && (hc >= 1) && (hc < 65);

        u64 acc[8];
        #pragma unroll
        for (int q = 0; q < 8; q++) acc[q] = c_w.b1[q];

        #pragma unroll
        for (int ky = 0; ky < 3; ky++) {
            #pragma unroll
            for (int kx = 0; kx < 7; kx++) {
                const int t = ky * 7 + kx;
                const u64 d = dup2(sx[hr + ky][hc + kx]);
                #pragma unroll
                for (int og = 0; og < 4; og++) {
                    ulonglong2 w = c_w.w1t[t][og];
                    acc[og * 2 + 0] = ffma2(w.x, d, acc[og * 2 + 0]);
                    acc[og * 2 + 1] = ffma2(w.y, d, acc[og * 2 + 1]);
                }
            }
        }
        #pragma unroll
        for (int kx = 0; kx < 3; kx++) {
            const int t = 21 + kx;
            const u64 d = dup2(sx[hr + 3][hc + kx]);
            #pragma unroll
            for (int og = 0; og < 4; og++) {
                ulonglong2 w = c_w.w1t[t][og];
                acc[og * 2 + 0] = ffma2(w.x, d, acc[og * 2 + 0]);
                acc[og * 2 + 1] = ffma2(w.y, d, acc[og * 2 + 1]);
            }
        }

        // relu + mask -> fp16 (hi only), swizzled STS.128 pair
        unsigned hiw[8];
        #pragma unroll
        for (int q = 0; q < 8; q++) {
            float2 v = unpack2(acc[q]);
            float a0 = ok ? fmaxf(v.x, 0.0f) : 0.0f;
            float a1 = ok ? fmaxf(v.y, 0.0f) : 0.0f;
            __half2 hh = __float22half2_rn(make_float2(a0, a1));
            hiw[q] = *reinterpret_cast<unsigned*>(&hh);
        }
        const int s0 = (m >> 2) & 1;   // chunk swizzle: physical = logical ^ s0
        uint4* row = reinterpret_cast<uint4*>(&A[m][0]);
        row[s0]     = make_uint4(hiw[0], hiw[1], hiw[2], hiw[3]);  // logical chunk 0
        row[1 - s0] = make_uint4(hiw[4], hiw[5], hiw[6], hiw[7]);  // logical chunk 1
    }
    __syncthreads();

    // ---- conv2 via mma (2-term, hoisted B) + conv3 + sigmoid ----
    {
        const unsigned a_b  = smem_u32(&A[0][0]);
        const unsigned bh_b = smem_u32(&Bh[0][0][0]);
        const unsigned bl_b = smem_u32(&Bl[0][0][0]);

        const unsigned arow  = lane & 15;
        const unsigned akoff = (lane >> 4) * 16;   // logical k-half byte offset
        const unsigned brow  = lane & 15;
        const unsigned bnoff = (lane >> 4) * 16;

        // hoist B fragments: tile-invariant
        unsigned bh[5][4], bl[5][4];
        #pragma unroll
        for (int t = 0; t < 5; t++) {
            const unsigned bbyte = (unsigned)t * 512 + brow * 32 + bnoff;
            ldsm_x4t(bh_b + bbyte, bh[t][0], bh[t][1], bh[t][2], bh[t][3]);
            ldsm_x4t(bl_b + bbyte, bl[t][0], bl[t][1], bl[t][2], bl[t][3]);
        }

        // epilogue constants
        const int cb = (lane & 3) * 2;
        float b2c[4], w3c[4];
        #pragma unroll
        for (int j = 0; j < 2; j++) {
            b2c[j]     = cwf[1680 + cb + j];
            b2c[2 + j] = cwf[1680 + cb + 8 + j];
            w3c[j]     = cwf[1696 + cb + j];
            w3c[2 + j] = cwf[1696 + cb + 8 + j];
        }
        const float b3v = cwf[1712];

        const int shifts[5] = {0, 1, 2, 66, 67};

        for (int tile = wid; tile < 33; tile += 8) {
            const int m0 = tile * 16;
            float d0[4] = {0.f, 0.f, 0.f, 0.f};
            float d1[4] = {0.f, 0.f, 0.f, 0.f};

            #pragma unroll
            for (int t = 0; t < 5; t++) {
                const unsigned row   = (unsigned)(m0 + shifts[t]) + arow;
                const unsigned rbyte = row * 32 + (akoff ^ ((row & 4u) << 2));
                unsigned a0, a1, a2, a3;
                ldsm_x4(a_b + rbyte, a0, a1, a2, a3);

                mma16816(d0[0], d0[1], d0[2], d0[3], a0, a1, a2, a3, bh[t][0], bh[t][1]);
                mma16816(d1[0], d1[1], d1[2], d1[3], a0, a1, a2, a3, bh[t][2], bh[t][3]);
                mma16816(d0[0], d0[1], d0[2], d0[3], a0, a1, a2, a3, bl[t][0], bl[t][1]);
                mma16816(d1[0], d1[1], d1[2], d1[3], a0, a1, a2, a3, bl[t][2], bl[t][3]);
            }

            float zA = 0.f, zB = 0.f;
            #pragma unroll
            for (int j = 0; j < 2; j++) {
                zA += fmaxf(d0[j]     + b2c[j],     0.0f) * w3c[j];
                zA += fmaxf(d1[j]     + b2c[2 + j], 0.0f) * w3c[2 + j];
                zB += fmaxf(d0[2 + j] + b2c[j],     0.0f) * w3c[j];
                zB += fmaxf(d1[2 + j] + b2c[2 + j], 0.0f) * w3c[2 + j];
            }
            zA += __shfl_xor_sync(0xffffffffu, zA, 1);
            zA += __shfl_xor_sync(0xffffffffu, zA, 2);
            zB += __shfl_xor_sync(0xffffffffu, zB, 1);
            zB += __shfl_xor_sync(0xffffffffu, zB, 2);

            if ((lane & 3) == 0) {
                const int g = lane >> 2;
                #pragma unroll
                for (int s = 0; s < 2; s++) {
                    const int m = m0 + g + s * 8;
                    const float z = (s == 0 ? zA : zB) + b3v;
                    const int r = m / 66;
                    const int c = m - r * 66;
                    if (c < 64 && r < 8) {
                        float y = 1.0f / (1.0f + __expf(-z));
                        out[img * (IMG_H * IMG_W) + (r0 + r) * IMG_W + c] = y;
                    }
                }
            }
        }
    }
}

extern "C" void kernel_launch(void* const* d_in, const int* in_sizes, int n_in,
                              void* d_out, int out_size) {
    const float* x  = (const float*)d_in[0];
    const float* w1 = (const float*)d_in[1];
    const float* b1 = (const float*)d_in[2];
    const float* w2 = (const float*)d_in[3];
    const float* b2 = (const float*)d_in[4];
    const float* w3 = (const float*)d_in[5];
    const float* b3 = (const float*)d_in[6];
    float* out = (float*)d_out;

    cudaFuncSetAttribute(pixelcnn_fused,
                         cudaFuncAttributePreferredSharedMemoryCarveout, 100);

    pixelcnn_prep<<<1, 256>>>(w1, b1, w2, b2, w3, b3);

    void* g_addr = nullptr;
    cudaGetSymbolAddress(&g_addr, g_w);
    cudaMemcpyToSymbolAsync(c_w, g_addr, sizeof(PackedW), 0,
                            cudaMemcpyDeviceToDevice, 0);

    dim3 grid(IMG_H / TH, 1024);
    pixelcnn_fused<<<grid, 256>>>(x, out);
}

// round 15
// speedup vs baseline: 1.4104x; 1.0991x over previous
#include <cuda_runtime.h>
#include <cuda_fp16.h>
#include <math.h>

// PixelCNN fused forward.
// R15 = R14 + occupancy push: Bl fragments de-hoisted (reloaded per tile),
//       __launch_bounds__(256,5) -> target ~50 regs, 5 CTAs/SM.
//   conv1 scalar FFMA2 on all 256 threads -> A = fp16(relu(h1));
//   conv2 via mma.m16n8k16: A*Bh + A*Bl (2-term weight split, rel_err ~1e-5);
//   XOR 16B-chunk swizzle on A (conflict-free ldsm). smem 28KB.

#define IMG_H 64
#define IMG_W 64
#define NCH   16
#define TH    8
#define XR    (TH + 4)
#define XC    (IMG_W + 8)
#define AROWS 596          // 9*66 = 594 used + 2 pad

typedef unsigned long long u64;

struct PackedW {
    ulonglong2 w1t[24][4];    // [tap][ocgroup] fp32 pairs
    ulonglong2 w2[16][5][4];  // [ic][tap][ocgroup] fp32
    u64   b1[8];
    u64   b2[8];
    float w3[16];
    float b3;
    float pad[3];
};

__device__   PackedW g_w;
__constant__ PackedW c_w;

__device__ __forceinline__ u64 ffma2(u64 a, u64 b, u64 c) {
    u64 d;
    asm("fma.rn.f32x2 %0, %1, %2, %3;" : "=l"(d) : "l"(a), "l"(b), "l"(c));
    return d;
}
__device__ __forceinline__ u64 dup2(float x) {
    u64 d;
    asm("mov.b64 %0, {%1, %1};" : "=l"(d) : "f"(x));
    return d;
}
__device__ __forceinline__ float2 unpack2(u64 v) {
    float2 r;
    asm("mov.b64 {%0, %1}, %2;" : "=f"(r.x), "=f"(r.y) : "l"(v));
    return r;
}
__device__ __forceinline__ unsigned smem_u32(const void* p) {
    unsigned a;
    asm("{ .reg .u64 t; cvta.to.shared.u64 t, %1; cvt.u32.u64 %0, t; }"
        : "=r"(a) : "l"(p));
    return a;
}
__device__ __forceinline__ void ldsm_x4(unsigned addr, unsigned& r0, unsigned& r1,
                                        unsigned& r2, unsigned& r3) {
    asm volatile("ldmatrix.sync.aligned.m8n8.x4.shared.b16 {%0,%1,%2,%3}, [%4];"
                 : "=r"(r0), "=r"(r1), "=r"(r2), "=r"(r3) : "r"(addr));
}
__device__ __forceinline__ void ldsm_x4t(unsigned addr, unsigned& r0, unsigned& r1,
                                         unsigned& r2, unsigned& r3) {
    asm volatile("ldmatrix.sync.aligned.m8n8.x4.trans.shared.b16 {%0,%1,%2,%3}, [%4];"
                 : "=r"(r0), "=r"(r1), "=r"(r2), "=r"(r3) : "r"(addr));
}
__device__ __forceinline__ void mma16816(float& d0, float& d1, float& d2, float& d3,
                                         unsigned a0, unsigned a1, unsigned a2, unsigned a3,
                                         unsigned b0, unsigned b1) {
    asm volatile(
        "mma.sync.aligned.m16n8k16.row.col.f32.f16.f16.f32 "
        "{%0,%1,%2,%3}, {%4,%5,%6,%7}, {%8,%9}, {%0,%1,%2,%3};"
        : "+f"(d0), "+f"(d1), "+f"(d2), "+f"(d3)
        : "r"(a0), "r"(a1), "r"(a2), "r"(a3), "r"(b0), "r"(b1));
}

// ---- prep: pack masked weights into g_w (float view) ----
__global__ void pixelcnn_prep(const float* __restrict__ w1, const float* __restrict__ b1,
                              const float* __restrict__ w2, const float* __restrict__ b2,
                              const float* __restrict__ w3, const float* __restrict__ b3)
{
    float* dst = reinterpret_cast<float*>(&g_w);
    const int tid = threadIdx.x;

    for (int idx = tid; idx < 24 * NCH; idx += 256) {
        int t = idx / NCH, oc = idx % NCH;
        int ky, kx;
        if (t < 21) { ky = t / 7; kx = t % 7; }
        else        { ky = 3;     kx = t - 21; }
        dst[idx] = w1[oc * 49 + ky * 7 + kx];
    }
    for (int idx = tid; idx < NCH * 5 * NCH; idx += 256) {
        int ic  = idx / (5 * NCH);
        int rem = idx % (5 * NCH);
        int t   = rem / NCH;
        int oc  = rem % NCH;
        int ky, kx;
        if (t < 3) { ky = 0; kx = t; }
        else       { ky = 1; kx = t - 3; }
        dst[384 + idx] = w2[((oc * NCH + ic) * 3 + ky) * 3 + kx];
    }
    if (tid < NCH) {
        dst[1664 + tid] = b1[tid];
        dst[1680 + tid] = b2[tid];
        dst[1696 + tid] = w3[tid];
    }
    if (tid == 0) dst[1712] = b3[0];
}

__global__ __launch_bounds__(256, 5)
void pixelcnn_fused(const float* __restrict__ x, float* __restrict__ out)
{
    __shared__ __align__(16) float   sx[XR][XC];        // 3456 B
    __shared__ __align__(16) __half  A[AROWS][16];      // 19072 B (swizzled chunks)
    __shared__ __align__(16) __half  Bh[5][16][16];     // 2560 B
    __shared__ __align__(16) __half  Bl[5][16][16];     // 2560 B

    const int tid  = threadIdx.x;
    const int lane = tid & 31;
    const int wid  = tid >> 5;
    const int img  = blockIdx.y;
    const int r0   = blockIdx.x * TH;
    const float* __restrict__ xim = x + img * (IMG_H * IMG_W);
    const float* cwf = reinterpret_cast<const float*>(&c_w);

    // ---- load x halo tile (zero padded) ----
    for (int idx = tid; idx < XR * XC; idx += 256) {
        int i = idx / XC, j = idx % XC;
        int gr = r0 - 4 + i;
        int gc = j - 4;
        float v = 0.0f;
        if (gr >= 0 && gr < IMG_H && gc >= 0 && gc < IMG_W)
            v = xim[gr * IMG_W + gc];
        sx[i][j] = v;
    }

    // ---- build conv2 B matrices (hi/lo f16 weight split) ----
    for (int idx = tid; idx < 16 * 5 * 16; idx += 256) {
        int ic  = idx / 80;
        int rem = idx % 80;
        int t   = rem / 16;
        int oc  = rem % 16;
        float v = cwf[384 + ic * 80 + t * 16 + oc];
        __half hi = __float2half_rn(v);
        __half lo = __float2half_rn(v - __half2float(hi));
        Bh[t][ic][oc] = hi;
        Bl[t][ic][oc] = lo;
    }

    // ---- zero A pad rows (594, 595) ----
    if (tid < 16) {
        int rr = 594 + (tid >> 3);
        int cc = (tid & 7) * 2;
        *reinterpret_cast<unsigned*>(&A[rr][cc]) = 0u;
    }
    __syncthreads();

    // ---- conv1: all 256 threads, pixels strided by 256, all 16 oc ----
    for (int m = tid; m < 594; m += 256) {
        const int hr = m / 66;
        const int hc = m - hr * 66;
        const int grow = r0 - 1 + hr;
        const bool ok = (grow >= 0) && (hc >= 1) && (hc < 65);

        u64 acc[8];
        #pragma unroll
        for (int q = 0; q < 8; q++) acc[q] = c_w.b1[q];

        #pragma unroll
        for (int ky = 0; ky < 3; ky++) {
            #pragma unroll
            for (int kx = 0; kx < 7; kx++) {
                const int t = ky * 7 + kx;
                const u64 d = dup2(sx[hr + ky][hc + kx]);
                #pragma unroll
                for (int og = 0; og < 4; og++) {
                    ulonglong2 w = c_w.w1t[t][og];
                    acc[og * 2 + 0] = ffma2(w.x, d, acc[og * 2 + 0]);
                    acc[og * 2 + 1] = ffma2(w.y, d, acc[og * 2 + 1]);
                }
            }
        }
        #pragma unroll
        for (int kx = 0; kx < 3; kx++) {
            const int t = 21 + kx;
            const u64 d = dup2(sx[hr + 3][hc + kx]);
            #pragma unroll
            for (int og = 0; og < 4; og++) {
                ulonglong2 w = c_w.w1t[t][og];
                acc[og * 2 + 0] = ffma2(w.x, d, acc[og * 2 + 0]);
                acc[og * 2 + 1] = ffma2(w.y, d, acc[og * 2 + 1]);
            }
        }

        // relu + mask -> fp16, swizzled STS.128 pair
        unsigned hiw[8];
        #pragma unroll
        for (int q = 0; q < 8; q++) {
            float2 v = unpack2(acc[q]);
            float a0 = ok ? fmaxf(v.x, 0.0f) : 0.0f;
            float a1 = ok ? fmaxf(v.y, 0.0f) : 0.0f;
            __half2 hh = __float22half2_rn(make_float2(a0, a1));
            hiw[q] = *reinterpret_cast<unsigned*>(&hh);
        }
        const int s0 = (m >> 2) & 1;   // chunk swizzle: physical = logical ^ s0
        uint4* row = reinterpret_cast<uint4*>(&A[m][0]);
        row[s0]     = make_uint4(hiw[0], hiw[1], hiw[2], hiw[3]);
        row[1 - s0] = make_uint4(hiw[4], hiw[5], hiw[6], hiw[7]);
    }
    __syncthreads();

    // ---- conv2 via mma (2-term; Bh hoisted, Bl per-tile) + conv3 + sigmoid ----
    {
        const unsigned a_b  = smem_u32(&A[0][0]);
        const unsigned bh_b = smem_u32(&Bh[0][0][0]);
        const unsigned bl_b = smem_u32(&Bl[0][0][0]);

        const unsigned arow  = lane & 15;
        const unsigned akoff = (lane >> 4) * 16;
        const unsigned brow  = lane & 15;
        const unsigned bnoff = (lane >> 4) * 16;
        const unsigned blane = brow * 32 + bnoff;

        // hoist only Bh fragments (20 regs); Bl reloaded per tile
        unsigned bh[5][4];
        #pragma unroll
        for (int t = 0; t < 5; t++) {
            const unsigned bbyte = (unsigned)t * 512 + blane;
            ldsm_x4t(bh_b + bbyte, bh[t][0], bh[t][1], bh[t][2], bh[t][3]);
        }

        // epilogue constants
        const int cb = (lane & 3) * 2;
        float b2c[4], w3c[4];
        #pragma unroll
        for (int j = 0; j < 2; j++) {
            b2c[j]     = cwf[1680 + cb + j];
            b2c[2 + j] = cwf[1680 + cb + 8 + j];
            w3c[j]     = cwf[1696 + cb + j];
            w3c[2 + j] = cwf[1696 + cb + 8 + j];
        }
        const float b3v = cwf[1712];

        const int shifts[5] = {0, 1, 2, 66, 67};

        for (int tile = wid; tile < 33; tile += 8) {
            const int m0 = tile * 16;
            float d0[4] = {0.f, 0.f, 0.f, 0.f};
            float d1[4] = {0.f, 0.f, 0.f, 0.f};

            #pragma unroll
            for (int t = 0; t < 5; t++) {
                const unsigned row   = (unsigned)(m0 + shifts[t]) + arow;
                const unsigned rbyte = row * 32 + (akoff ^ ((row & 4u) << 2));
                unsigned a0, a1, a2, a3;
                ldsm_x4(a_b + rbyte, a0, a1, a2, a3);
                unsigned l0, l1, l2, l3;
                ldsm_x4t(bl_b + (unsigned)t * 512 + blane, l0, l1, l2, l3);

                mma16816(d0[0], d0[1], d0[2], d0[3], a0, a1, a2, a3, bh[t][0], bh[t][1]);
                mma16816(d1[0], d1[1], d1[2], d1[3], a0, a1, a2, a3, bh[t][2], bh[t][3]);
                mma16816(d0[0], d0[1], d0[2], d0[3], a0, a1, a2, a3, l0, l1);
                mma16816(d1[0], d1[1], d1[2], d1[3], a0, a1, a2, a3, l2, l3);
            }

            float zA = 0.f, zB = 0.f;
            #pragma unroll
            for (int j = 0; j < 2; j++) {
                zA += fmaxf(d0[j]     + b2c[j],     0.0f) * w3c[j];
                zA += fmaxf(d1[j]     + b2c[2 + j], 0.0f) * w3c[2 + j];
                zB += fmaxf(d0[2 + j] + b2c[j],     0.0f) * w3c[j];
                zB += fmaxf(d1[2 + j] + b2c[2 + j], 0.0f) * w3c[2 + j];
            }
            zA += __shfl_xor_sync(0xffffffffu, zA, 1);
            zA += __shfl_xor_sync(0xffffffffu, zA, 2);
            zB += __shfl_xor_sync(0xffffffffu, zB, 1);
            zB += __shfl_xor_sync(0xffffffffu, zB, 2);

            if ((lane & 3) == 0) {
                const int g = lane >> 2;
                #pragma unroll
                for (int s = 0; s < 2; s++) {
                    const int m = m0 + g + s * 8;
                    const float z = (s == 0 ? zA : zB) + b3v;
                    const int r = m / 66;
                    const int c = m - r * 66;
                    if (c < 64 && r < 8) {
                        float y = 1.0f / (1.0f + __expf(-z));
                        out[img * (IMG_H * IMG_W) + (r0 + r) * IMG_W + c] = y;
                    }
                }
            }
        }
    }
}

extern "C" void kernel_launch(void* const* d_in, const int* in_sizes, int n_in,
                              void* d_out, int out_size) {
    const float* x  = (const float*)d_in[0];
    const float* w1 = (const float*)d_in[1];
    const float* b1 = (const float*)d_in[2];
    const float* w2 = (const float*)d_in[3];
    const float* b2 = (const float*)d_in[4];
    const float* w3 = (const float*)d_in[5];
    const float* b3 = (const float*)d_in[6];
    float* out = (float*)d_out;

    cudaFuncSetAttribute(pixelcnn_fused,
                         cudaFuncAttributePreferredSharedMemoryCarveout, 100);

    pixelcnn_prep<<<1, 256>>>(w1, b1, w2, b2, w3, b3);

    void* g_addr = nullptr;
    cudaGetSymbolAddress(&g_addr, g_w);
    cudaMemcpyToSymbolAsync(c_w, g_addr, sizeof(PackedW), 0,
                            cudaMemcpyDeviceToDevice, 0);

    dim3 grid(IMG_H / TH, 1024);
    pixelcnn_fused<<<grid, 256>>>(x, out);
}